// round 2
// baseline (speedup 1.0000x reference)
#include <cuda_runtime.h>

#define BB 16384
#define TT 64
typedef unsigned long long u64;

// Ping-pong layer buffers: [B][T][64] (fwd in [0:32), bwd in [32:64))
__device__ float g_buf0[BB * TT * 64];
__device__ float g_buf1[BB * TT * 64];

__device__ __forceinline__ float sigf(float x) {
    return __fdividef(1.0f, 1.0f + __expf(-x));
}
__device__ __forceinline__ float tanh_fast(float x) {
    float e = __expf(-2.0f * x);
    return __fdividef(1.0f - e, 1.0f + e);
}

// Packed f32x2 FMA: 2 MACs per instruction (ptxas never emits this from C++).
__device__ __forceinline__ u64 fma2(u64 a, u64 b, u64 c) {
    u64 d;
    asm("fma.rn.f32x2 %0, %1, %2, %3;" : "=l"(d) : "l"(a), "l"(b), "l"(c));
    return d;
}
__device__ __forceinline__ float2 unpk(u64 v) {
    float2 r;
    asm("mov.b64 {%0, %1}, %2;" : "=f"(r.x), "=f"(r.y) : "l"(v));
    return r;
}
__device__ __forceinline__ float hsum2(u64 a, u64 b) {
    float2 x = unpk(a), y = unpk(b);
    return (x.x + x.y) + (y.x + y.y);
}

// ---------------------------------------------------------------------------
// Layer 0: input K=2. One warp per (batch, dir). Lane j owns hidden unit j,
// computes all 3 gates with f32x2 packed FMAs. Whh rows in register pairs,
// h broadcast via smem (double buffered, one __syncwarp per step).
// ---------------------------------------------------------------------------
__global__ __launch_bounds__(128) void gru_l0(
    const float* __restrict__ x,
    const float* __restrict__ Wih0, const float* __restrict__ Whh0,
    const float* __restrict__ bih0, const float* __restrict__ bhh0)
{
    const int w = threadIdx.x >> 5, lane = threadIdx.x & 31;
    const int b = blockIdx.x * 4 + w;
    const int dir = blockIdx.y;

    __shared__ __align__(16) float hb[4][2][32];

    const float* wi = Wih0 + dir * 96 * 2;
    const float* wh = Whh0 + dir * 96 * 32;
    const float* bi = bih0 + dir * 96;
    const float* bh = bhh0 + dir * 96;

    const float wx0 = wi[(lane) * 2 + 0],      wx1 = wi[(lane) * 2 + 1];
    const float wz0 = wi[(32 + lane) * 2 + 0], wz1 = wi[(32 + lane) * 2 + 1];
    const float wn0 = wi[(64 + lane) * 2 + 0], wn1 = wi[(64 + lane) * 2 + 1];

    u64 whr2[16], whz2[16], whn2[16];
#pragma unroll
    for (int k = 0; k < 16; k++) {
        whr2[k] = ((const u64*)(wh + (size_t)(lane) * 32))[k];
        whz2[k] = ((const u64*)(wh + (size_t)(32 + lane) * 32))[k];
        whn2[k] = ((const u64*)(wh + (size_t)(64 + lane) * 32))[k];
    }
    const float br  = bi[lane] + bh[lane];
    const float bz  = bi[32 + lane] + bh[32 + lane];
    const float bxn = bi[64 + lane];
    const float bhn = bh[64 + lane];

    float h = 0.0f;
    hb[w][0][lane] = 0.0f;
    __syncwarp();

    const float* xp = x + (size_t)b * TT * 2;
    float* outp = g_buf0 + (size_t)b * TT * 64 + dir * 32 + lane;

    for (int t = 0; t < TT; t++) {
        const int te = dir ? (TT - 1 - t) : t;
        const float2 xv = *(const float2*)&xp[te * 2];

        const float sr = fmaf(xv.y, wx1, fmaf(xv.x, wx0, br));
        const float sz = fmaf(xv.y, wz1, fmaf(xv.x, wz0, bz));
        const float sn = fmaf(xv.y, wn1, fmaf(xv.x, wn0, bxn));

        u64 r0 = 0ull, r1 = 0ull, z0 = 0ull, z1 = 0ull, n0 = 0ull, n1 = 0ull;
        const ulonglong2* h4 = (const ulonglong2*)hb[w][t & 1];
#pragma unroll
        for (int c = 0; c < 8; c++) {
            ulonglong2 hv = h4[c];
            r0 = fma2(hv.x, whr2[2 * c],     r0);
            r1 = fma2(hv.y, whr2[2 * c + 1], r1);
            z0 = fma2(hv.x, whz2[2 * c],     z0);
            z1 = fma2(hv.y, whz2[2 * c + 1], z1);
            n0 = fma2(hv.x, whn2[2 * c],     n0);
            n1 = fma2(hv.y, whn2[2 * c + 1], n1);
        }
        const float r = sigf(sr + hsum2(r0, r1));
        const float z = sigf(sz + hsum2(z0, z1));
        const float n = tanh_fast(fmaf(r, bhn + hsum2(n0, n1), sn));
        h = fmaf(z, h - n, n);

        hb[w][(t + 1) & 1][lane] = h;
        outp[(size_t)te * 64] = h;
        __syncwarp();
    }
}

// ---------------------------------------------------------------------------
// Layers 1/2: input K=64. 3 warps per (batch, dir), one gate per warp so all
// weights fit in register pairs (f32x2). Raw gate accumulators exchanged via
// double-buffered smem; ONE __syncthreads per step — every warp redundantly
// computes the h update and keeps its own copy of h in its own smem buffer.
//   phase = 0: buf0 -> buf1 (layer 1);  phase = 1: buf1 -> buf0 (layer 2)
// ---------------------------------------------------------------------------
__global__ __launch_bounds__(96) void gru_l12(
    int phase,
    const float* __restrict__ Wih, const float* __restrict__ Whh,
    const float* __restrict__ bih, const float* __restrict__ bhh)
{
    const float* in  = phase ? g_buf1 : g_buf0;
    float*       out = phase ? g_buf0 : g_buf1;

    const int w = threadIdx.x >> 5, lane = threadIdx.x & 31;
    const int b = blockIdx.x, dir = blockIdx.y;
    const int row = w * 32 + lane;

    const float* wi = Wih + ((size_t)phase * 2 + dir) * 96 * 64;
    const float* wh = Whh + ((size_t)phase * 2 + dir) * 96 * 32;
    const float* bi = bih + ((size_t)phase * 2 + dir) * 96;
    const float* bh = bhh + ((size_t)phase * 2 + dir) * 96;

    u64 wx2[32], wh2[16];
#pragma unroll
    for (int k = 0; k < 32; k++)
        wx2[k] = ((const u64*)(wi + (size_t)row * 64))[k];
#pragma unroll
    for (int k = 0; k < 16; k++)
        wh2[k] = ((const u64*)(wh + (size_t)row * 32))[k];
    const float bx = bi[row];
    const float bhv = bh[row];

    __shared__ __align__(16) float sx[2][64];
    __shared__ float s_r[2][32];
    __shared__ float s_z[2][32];
    __shared__ float s_xn[2][32];
    __shared__ float s_hn[2][32];
    __shared__ __align__(16) float sh[3][2][32];

    const float* inb = in + (size_t)b * TT * 64;
    float* outb = out + (size_t)b * TT * 64 + dir * 32;

    sh[w][0][lane] = 0.0f;
    {
        const int te0 = dir ? (TT - 1) : 0;
        if (w == 0) sx[0][lane]      = inb[(size_t)te0 * 64 + lane];
        if (w == 1) sx[0][32 + lane] = inb[(size_t)te0 * 64 + 32 + lane];
    }
    __syncthreads();

    float h = 0.0f;  // every warp tracks an identical copy

    for (int t = 0; t < TT; t++) {
        const int buf = t & 1, nbuf = buf ^ 1;
        const int te = dir ? (TT - 1 - t) : t;

        // Prefetch next input row (warps 0/1) into the other sx buffer.
        if (t + 1 < TT) {
            const int ten = dir ? (te - 1) : (te + 1);
            if (w == 0) sx[nbuf][lane]      = inb[(size_t)ten * 64 + lane];
            if (w == 1) sx[nbuf][32 + lane] = inb[(size_t)ten * 64 + 32 + lane];
        }

        // Input-gate GEMV: 64 MACs as 32 f32x2 FMAs.
        u64 ax0 = 0ull, ax1 = 0ull;
        const ulonglong2* x4 = (const ulonglong2*)sx[buf];
#pragma unroll
        for (int c = 0; c < 16; c++) {
            ulonglong2 v = x4[c];
            ax0 = fma2(v.x, wx2[2 * c],     ax0);
            ax1 = fma2(v.y, wx2[2 * c + 1], ax1);
        }
        // Recurrent GEMV: 32 MACs as 16 f32x2 FMAs, from this warp's own h copy.
        u64 ah0 = 0ull, ah1 = 0ull;
        const ulonglong2* h4 = (const ulonglong2*)sh[w][buf];
#pragma unroll
        for (int c = 0; c < 8; c++) {
            ulonglong2 v = h4[c];
            ah0 = fma2(v.x, wh2[2 * c],     ah0);
            ah1 = fma2(v.y, wh2[2 * c + 1], ah1);
        }
        const float accx = hsum2(ax0, ax1) + bx;
        const float acch = hsum2(ah0, ah1) + bhv;

        if (w == 0)      s_r[buf][lane] = accx + acch;
        else if (w == 1) s_z[buf][lane] = accx + acch;
        else             { s_xn[buf][lane] = accx; s_hn[buf][lane] = acch; }
        __syncthreads();

        // All warps redundantly compute the update (keeps h local to each warp).
        const float r = sigf(s_r[buf][lane]);
        const float z = sigf(s_z[buf][lane]);
        const float n = tanh_fast(fmaf(r, s_hn[buf][lane], s_xn[buf][lane]));
        h = fmaf(z, h - n, n);

        sh[w][nbuf][lane] = h;
        if (w == 2) outb[(size_t)te * 64 + lane] = h;
        __syncwarp();
    }
}

// ---------------------------------------------------------------------------
// Final FC: y = tanh(out @ Wfc.T + bfc). Warp per row, shuffle reduction.
// ---------------------------------------------------------------------------
__global__ __launch_bounds__(256) void fc_kernel(
    const float* __restrict__ Wfc, const float* __restrict__ bfc,
    float* __restrict__ outp)
{
    const float* in = g_buf0;  // layer 2 output
    const int lane = threadIdx.x & 31;
    const int warp = (blockIdx.x * blockDim.x + threadIdx.x) >> 5;
    const int nwarps = (gridDim.x * blockDim.x) >> 5;

    const float w0a = __ldg(&Wfc[2 * lane]),      w0b = __ldg(&Wfc[2 * lane + 1]);
    const float w1a = __ldg(&Wfc[64 + 2 * lane]), w1b = __ldg(&Wfc[64 + 2 * lane + 1]);
    const float b0 = __ldg(&bfc[0]), b1 = __ldg(&bfc[1]);

    const int nrows = BB * TT;
    for (int row = warp; row < nrows; row += nwarps) {
        float2 xv = *(const float2*)&in[(size_t)row * 64 + 2 * lane];
        float y0 = fmaf(xv.y, w0b, xv.x * w0a);
        float y1 = fmaf(xv.y, w1b, xv.x * w1a);
#pragma unroll
        for (int o = 16; o > 0; o >>= 1) {
            y0 += __shfl_xor_sync(0xFFFFFFFFu, y0, o);
            y1 += __shfl_xor_sync(0xFFFFFFFFu, y1, o);
        }
        if (lane == 0) {
            float2 r;
            r.x = tanh_fast(y0 + b0);
            r.y = tanh_fast(y1 + b1);
            *(float2*)&outp[(size_t)row * 2] = r;
        }
    }
}

// ---------------------------------------------------------------------------
extern "C" void kernel_launch(void* const* d_in, const int* in_sizes, int n_in,
                              void* d_out, int out_size)
{
    const float* x    = (const float*)d_in[0];
    const float* Wih0 = (const float*)d_in[1];
    const float* Whh0 = (const float*)d_in[2];
    const float* bih0 = (const float*)d_in[3];
    const float* bhh0 = (const float*)d_in[4];
    const float* Wih  = (const float*)d_in[5];
    const float* Whh  = (const float*)d_in[6];
    const float* bih  = (const float*)d_in[7];
    const float* bhh  = (const float*)d_in[8];
    const float* Wfc  = (const float*)d_in[9];
    const float* bfc  = (const float*)d_in[10];
    float* out = (float*)d_out;

    gru_l0<<<dim3(BB / 4, 2), 128>>>(x, Wih0, Whh0, bih0, bhh0);
    gru_l12<<<dim3(BB, 2), 96>>>(0, Wih, Whh, bih, bhh);
    gru_l12<<<dim3(BB, 2), 96>>>(1, Wih, Whh, bih, bhh);
    fc_kernel<<<2048, 256>>>(Wfc, bfc, out);
}

// round 3
// speedup vs baseline: 2.1025x; 2.1025x over previous
#include <cuda_runtime.h>

#define BB 16384
#define TT 64

// Ping-pong layer buffers: [B][T][64] (fwd in [0:32), bwd in [32:64))
__device__ float g_buf0[BB * TT * 64];
__device__ float g_buf1[BB * TT * 64];
// Input-gate pre-activations for the current layer: [B][T][192]
// row g = dir*96 + (gate*32 + j), includes bih.
__device__ float g_xg[(size_t)BB * TT * 192];

__device__ __forceinline__ float sigf(float x) {
    return __fdividef(1.0f, 1.0f + __expf(-x));
}
__device__ __forceinline__ float tanh_fast(float x) {
    float e = __expf(-2.0f * x);
    return __fdividef(1.0f - e, 1.0f + e);
}

// ---------------------------------------------------------------------------
// Layer 0: input K=2. One warp per (batch, dir). Lane j owns hidden unit j,
// computes all 3 gates. Whh rows in registers; x staged in smem once;
// h broadcast via smem double buffer, one __syncwarp per step.
// ---------------------------------------------------------------------------
__global__ __launch_bounds__(128) void gru_l0(
    const float* __restrict__ x,
    const float* __restrict__ Wih0, const float* __restrict__ Whh0,
    const float* __restrict__ bih0, const float* __restrict__ bhh0)
{
    const int w = threadIdx.x >> 5, lane = threadIdx.x & 31;
    const int b = blockIdx.x * 4 + w;
    const int dir = blockIdx.y;

    __shared__ __align__(16) float hb[4][2][32];
    __shared__ __align__(16) float xs[4][128];   // whole input sequence per warp

    const float* wi = Wih0 + dir * 96 * 2;
    const float* wh = Whh0 + dir * 96 * 32;
    const float* bi = bih0 + dir * 96;
    const float* bh = bhh0 + dir * 96;

    // Stage x[b] (64 steps x 2) into smem: 128 floats, 4 per lane.
    {
        float4 v = *(const float4*)(x + (size_t)b * 128 + lane * 4);
        *(float4*)&xs[w][lane * 4] = v;
    }

    const float wx0 = wi[(lane) * 2 + 0],      wx1 = wi[(lane) * 2 + 1];
    const float wz0 = wi[(32 + lane) * 2 + 0], wz1 = wi[(32 + lane) * 2 + 1];
    const float wn0 = wi[(64 + lane) * 2 + 0], wn1 = wi[(64 + lane) * 2 + 1];

    float whr[32], whz[32], whn[32];
#pragma unroll
    for (int k = 0; k < 32; k += 4) {
        float4 a = *(const float4*)&wh[(lane) * 32 + k];
        whr[k] = a.x; whr[k + 1] = a.y; whr[k + 2] = a.z; whr[k + 3] = a.w;
        float4 c = *(const float4*)&wh[(32 + lane) * 32 + k];
        whz[k] = c.x; whz[k + 1] = c.y; whz[k + 2] = c.z; whz[k + 3] = c.w;
        float4 d = *(const float4*)&wh[(64 + lane) * 32 + k];
        whn[k] = d.x; whn[k + 1] = d.y; whn[k + 2] = d.z; whn[k + 3] = d.w;
    }
    const float br  = bi[lane] + bh[lane];
    const float bz  = bi[32 + lane] + bh[32 + lane];
    const float bxn = bi[64 + lane];
    const float bhn = bh[64 + lane];

    float h = 0.0f;
    hb[w][0][lane] = 0.0f;
    __syncwarp();

    float* outp = g_buf0 + (size_t)b * TT * 64 + dir * 32 + lane;

    for (int t = 0; t < TT; t++) {
        const int te = dir ? (TT - 1 - t) : t;
        const float x0 = xs[w][te * 2 + 0];
        const float x1 = xs[w][te * 2 + 1];

        float sr0 = fmaf(x1, wx1, fmaf(x0, wx0, br)),  sr1 = 0.f;
        float sz0 = fmaf(x1, wz1, fmaf(x0, wz0, bz)),  sz1 = 0.f;
        float sn0 = bhn, sn1 = 0.f;

        const float4* h4 = (const float4*)hb[w][t & 1];
#pragma unroll
        for (int c = 0; c < 8; c++) {
            float4 v = h4[c];
            sr0 = fmaf(v.x, whr[4 * c + 0], sr0);
            sr0 = fmaf(v.y, whr[4 * c + 1], sr0);
            sr1 = fmaf(v.z, whr[4 * c + 2], sr1);
            sr1 = fmaf(v.w, whr[4 * c + 3], sr1);
            sz0 = fmaf(v.x, whz[4 * c + 0], sz0);
            sz0 = fmaf(v.y, whz[4 * c + 1], sz0);
            sz1 = fmaf(v.z, whz[4 * c + 2], sz1);
            sz1 = fmaf(v.w, whz[4 * c + 3], sz1);
            sn0 = fmaf(v.x, whn[4 * c + 0], sn0);
            sn0 = fmaf(v.y, whn[4 * c + 1], sn0);
            sn1 = fmaf(v.z, whn[4 * c + 2], sn1);
            sn1 = fmaf(v.w, whn[4 * c + 3], sn1);
        }
        const float r = sigf(sr0 + sr1);
        const float z = sigf(sz0 + sz1);
        const float n = tanh_fast(fmaf(r, sn0 + sn1, fmaf(x1, wn1, fmaf(x0, wn0, bxn))));
        h = fmaf(z, h - n, n);

        hb[w][(t + 1) & 1][lane] = h;
        outp[(size_t)te * 64] = h;
        __syncwarp();
    }
}

// ---------------------------------------------------------------------------
// Input GEMM for layers 1/2:
//   xg[m][g] = sum_k in[m][k] * W[g][k] + bih[g],  m < B*T, g < 192, K = 64.
// Block: 256 thr, tile M=64 x N=96 (grid.y picks which 96-col half = dir).
// W half (96x64) and X tile (64x64) staged in smem (transposed, padded).
// Thread (tx=tid&15, ty=tid>>4): 4 rows (ty+16i) x 6 cols (tx*6..).
// ---------------------------------------------------------------------------
__global__ __launch_bounds__(256) void xgemm(
    int srcbuf,
    const float* __restrict__ W,     // [192][64] for this layer
    const float* __restrict__ bias)  // [192]
{
    const float* in = srcbuf ? g_buf1 : g_buf0;

    __shared__ __align__(16) float Ws[64][100];  // [k][c], c < 96 (+pad)
    __shared__ __align__(16) float Xs[64][65];   // [k][m], m < 64 (+pad)
    __shared__ float Bs[96];

    const int tid = threadIdx.x;
    const size_t m0 = (size_t)blockIdx.x * 64;
    const int c0 = blockIdx.y * 96;

    // Load W half transposed: W[c0+g][k] -> Ws[k][g]
    for (int q = tid; q < 96 * 16; q += 256) {
        const int g = q >> 4, k4 = (q & 15) << 2;
        float4 v = *(const float4*)&W[(size_t)(c0 + g) * 64 + k4];
        Ws[k4 + 0][g] = v.x; Ws[k4 + 1][g] = v.y;
        Ws[k4 + 2][g] = v.z; Ws[k4 + 3][g] = v.w;
    }
    if (tid < 96) Bs[tid] = bias[c0 + tid];

    // Load X tile transposed: in[m0+r][k] -> Xs[k][r]
    for (int q = tid; q < 64 * 16; q += 256) {
        const int r = q >> 4, k4 = (q & 15) << 2;
        float4 v = *(const float4*)&in[(m0 + r) * 64 + k4];
        Xs[k4 + 0][r] = v.x; Xs[k4 + 1][r] = v.y;
        Xs[k4 + 2][r] = v.z; Xs[k4 + 3][r] = v.w;
    }
    __syncthreads();

    const int tx = tid & 15, ty = tid >> 4;
    float acc[4][6];
#pragma unroll
    for (int i = 0; i < 4; i++)
#pragma unroll
        for (int j = 0; j < 6; j++) acc[i][j] = 0.0f;

#pragma unroll 16
    for (int k = 0; k < 64; k++) {
        float xv[4];
#pragma unroll
        for (int i = 0; i < 4; i++) xv[i] = Xs[k][ty + 16 * i];
        float2 w0 = *(const float2*)&Ws[k][tx * 6 + 0];
        float2 w1 = *(const float2*)&Ws[k][tx * 6 + 2];
        float2 w2 = *(const float2*)&Ws[k][tx * 6 + 4];
#pragma unroll
        for (int i = 0; i < 4; i++) {
            acc[i][0] = fmaf(xv[i], w0.x, acc[i][0]);
            acc[i][1] = fmaf(xv[i], w0.y, acc[i][1]);
            acc[i][2] = fmaf(xv[i], w1.x, acc[i][2]);
            acc[i][3] = fmaf(xv[i], w1.y, acc[i][3]);
            acc[i][4] = fmaf(xv[i], w2.x, acc[i][4]);
            acc[i][5] = fmaf(xv[i], w2.y, acc[i][5]);
        }
    }

    // Epilogue: add bias, store.
    float bv[6];
#pragma unroll
    for (int j = 0; j < 6; j++) bv[j] = Bs[tx * 6 + j];
#pragma unroll
    for (int i = 0; i < 4; i++) {
        const size_t m = m0 + ty + 16 * i;
        float* o = g_xg + m * 192 + c0 + tx * 6;
#pragma unroll
        for (int j = 0; j < 6; j += 2) {
            float2 v;
            v.x = acc[i][j] + bv[j];
            v.y = acc[i][j + 1] + bv[j + 1];
            *(float2*)&o[j] = v;
        }
    }
}

// ---------------------------------------------------------------------------
// Recurrence for layers 1/2. One warp per (batch, dir); lane j owns unit j,
// all 3 gates (96 weight regs, 96 FFMA/step). xg read with distance-4
// register-ring prefetch. No block barriers.
// ---------------------------------------------------------------------------
__global__ __launch_bounds__(128) void gru_rec(
    int dstbuf,
    const float* __restrict__ Whh,   // [2][96][32] for this layer
    const float* __restrict__ bhh)   // [192]
{
    float* out = dstbuf ? g_buf1 : g_buf0;

    const int w = threadIdx.x >> 5, lane = threadIdx.x & 31;
    const int b = blockIdx.x * 4 + w;
    const int dir = blockIdx.y;

    __shared__ __align__(16) float hb[4][2][32];

    const float* wh = Whh + dir * 96 * 32;
    const float* bh = bhh + dir * 96;

    float whr[32], whz[32], whn[32];
#pragma unroll
    for (int k = 0; k < 32; k += 4) {
        float4 a = *(const float4*)&wh[(lane) * 32 + k];
        whr[k] = a.x; whr[k + 1] = a.y; whr[k + 2] = a.z; whr[k + 3] = a.w;
        float4 c = *(const float4*)&wh[(32 + lane) * 32 + k];
        whz[k] = c.x; whz[k + 1] = c.y; whz[k + 2] = c.z; whz[k + 3] = c.w;
        float4 d = *(const float4*)&wh[(64 + lane) * 32 + k];
        whn[k] = d.x; whn[k + 1] = d.y; whn[k + 2] = d.z; whn[k + 3] = d.w;
    }
    const float br = bh[lane];
    const float bz = bh[32 + lane];
    const float bn = bh[64 + lane];

    const float* xgb = g_xg + (size_t)b * TT * 192 + dir * 96 + lane;
    float* outb = out + (size_t)b * TT * 64 + dir * 32 + lane;
    const int sd = dir ? -1 : 1;
    int te = dir ? (TT - 1) : 0;

    // Prefetch ring, distance 4.
    float pxr[4], pxz[4], pxn[4];
#pragma unroll
    for (int u = 0; u < 4; u++) {
        const float* p = xgb + (size_t)(te + sd * u) * 192;
        pxr[u] = p[0]; pxz[u] = p[32]; pxn[u] = p[64];
    }

    float h = 0.0f;
    hb[w][0][lane] = 0.0f;
    __syncwarp();

    for (int tb = 0; tb < TT; tb += 4) {
#pragma unroll
        for (int u = 0; u < 4; u++) {
            const int t = tb + u;
            // Prefetch t+4 (clamped to a valid address when past the end).
            const int tp = (t + 4 < TT) ? (te + sd * 4) : te;
            const float* p = xgb + (size_t)tp * 192;
            const float fr = p[0], fz = p[32], fn = p[64];

            float sr0 = pxr[u] + br, sr1 = 0.f;
            float sz0 = pxz[u] + bz, sz1 = 0.f;
            float sn0 = bn, sn1 = 0.f;

            const float4* h4 = (const float4*)hb[w][t & 1];
#pragma unroll
            for (int c = 0; c < 8; c++) {
                float4 v = h4[c];
                sr0 = fmaf(v.x, whr[4 * c + 0], sr0);
                sr0 = fmaf(v.y, whr[4 * c + 1], sr0);
                sr1 = fmaf(v.z, whr[4 * c + 2], sr1);
                sr1 = fmaf(v.w, whr[4 * c + 3], sr1);
                sz0 = fmaf(v.x, whz[4 * c + 0], sz0);
                sz0 = fmaf(v.y, whz[4 * c + 1], sz0);
                sz1 = fmaf(v.z, whz[4 * c + 2], sz1);
                sz1 = fmaf(v.w, whz[4 * c + 3], sz1);
                sn0 = fmaf(v.x, whn[4 * c + 0], sn0);
                sn0 = fmaf(v.y, whn[4 * c + 1], sn0);
                sn1 = fmaf(v.z, whn[4 * c + 2], sn1);
                sn1 = fmaf(v.w, whn[4 * c + 3], sn1);
            }
            const float r = sigf(sr0 + sr1);
            const float z = sigf(sz0 + sz1);
            const float n = tanh_fast(fmaf(r, sn0 + sn1, pxn[u]));
            h = fmaf(z, h - n, n);

            hb[w][(t + 1) & 1][lane] = h;
            outb[(size_t)te * 64] = h;
            pxr[u] = fr; pxz[u] = fz; pxn[u] = fn;
            te += sd;
            __syncwarp();
        }
    }
}

// ---------------------------------------------------------------------------
// Final FC: y = tanh(out @ Wfc.T + bfc). Warp per row, shuffle reduction.
// ---------------------------------------------------------------------------
__global__ __launch_bounds__(256) void fc_kernel(
    const float* __restrict__ Wfc, const float* __restrict__ bfc,
    float* __restrict__ outp)
{
    const float* in = g_buf0;  // layer 2 output
    const int lane = threadIdx.x & 31;
    const int warp = (blockIdx.x * blockDim.x + threadIdx.x) >> 5;
    const int nwarps = (gridDim.x * blockDim.x) >> 5;

    const float w0a = __ldg(&Wfc[2 * lane]),      w0b = __ldg(&Wfc[2 * lane + 1]);
    const float w1a = __ldg(&Wfc[64 + 2 * lane]), w1b = __ldg(&Wfc[64 + 2 * lane + 1]);
    const float b0 = __ldg(&bfc[0]), b1 = __ldg(&bfc[1]);

    const int nrows = BB * TT;
    for (int row = warp; row < nrows; row += nwarps) {
        float2 xv = *(const float2*)&in[(size_t)row * 64 + 2 * lane];
        float y0 = fmaf(xv.y, w0b, xv.x * w0a);
        float y1 = fmaf(xv.y, w1b, xv.x * w1a);
#pragma unroll
        for (int o = 16; o > 0; o >>= 1) {
            y0 += __shfl_xor_sync(0xFFFFFFFFu, y0, o);
            y1 += __shfl_xor_sync(0xFFFFFFFFu, y1, o);
        }
        if (lane == 0) {
            float2 r;
            r.x = tanh_fast(y0 + b0);
            r.y = tanh_fast(y1 + b1);
            *(float2*)&outp[(size_t)row * 2] = r;
        }
    }
}

// ---------------------------------------------------------------------------
extern "C" void kernel_launch(void* const* d_in, const int* in_sizes, int n_in,
                              void* d_out, int out_size)
{
    const float* x    = (const float*)d_in[0];
    const float* Wih0 = (const float*)d_in[1];
    const float* Whh0 = (const float*)d_in[2];
    const float* bih0 = (const float*)d_in[3];
    const float* bhh0 = (const float*)d_in[4];
    const float* Wih  = (const float*)d_in[5];
    const float* Whh  = (const float*)d_in[6];
    const float* bih  = (const float*)d_in[7];
    const float* bhh  = (const float*)d_in[8];
    const float* Wfc  = (const float*)d_in[9];
    const float* bfc  = (const float*)d_in[10];
    float* out = (float*)d_out;

    const int MB = (BB * TT) / 64;  // xgemm grid.x

    // Layer 0 -> buf0
    gru_l0<<<dim3(BB / 4, 2), 128>>>(x, Wih0, Whh0, bih0, bhh0);
    // Layer 1: buf0 -> xg -> buf1
    xgemm<<<dim3(MB, 2), 256>>>(0, Wih, bih);
    gru_rec<<<dim3(BB / 4, 2), 128>>>(1, Whh, bhh);
    // Layer 2: buf1 -> xg -> buf0
    xgemm<<<dim3(MB, 2), 256>>>(1, Wih + 192 * 64, bih + 192);
    gru_rec<<<dim3(BB / 4, 2), 128>>>(0, Whh + 192 * 32, bhh + 192);
    // FC
    fc_kernel<<<2048, 256>>>(Wfc, bfc, out);
}